// round 11
// baseline (speedup 1.0000x reference)
#include <cuda_runtime.h>

// Problem constants
#define NPX      65536      // 16 * 64 * 64 pixels
#define KCODES   1024
#define DDIM     256
#define HW       4096       // 64*64
#define TILE_PX  64
#define TILE_K   128
#define NKT      (KCODES / TILE_K)   // 8
#define NTILES   (NPX / TILE_PX)     // 1024
#define ZQ_ELEMS 16777216   // 16*256*64*64

// Scratch (device globals; zero-initialized at module load; last CTA of each
// launch resets them so every graph replay sees identical state)
__device__ float    g_esq[KCODES];
__device__ float    g_loss_acc;
__device__ unsigned g_done;
__device__ unsigned g_esq_flag;

// smem layout (floats):
//   z_s   [256][64]             16384
//   e_s   [128][257]            32896   (257 pad -> conflict-free compute reads)
//   esq_s [1024]                 1024
//   zsq_s [64]                     64
//   s_idx [64] (as int)            64
//   swsum [8]                       8
#define ZS_F   (DDIM * TILE_PX)          // 16384
#define ES_F   (TILE_K * 257)            // 32896
#define SMEM_FLOATS (ZS_F + ES_F + 1024 + 64 + 64 + 8)

// ---------------------------------------------------------------------------
// Main: fused esq pre-phase (CTA 0) + distance-GEMM + argmin + z_q + loss.
// GEMM structure and all FP chains identical to the proven round-10 kernel.
// ---------------------------------------------------------------------------
__global__ __launch_bounds__(256, 1)
void vq_main(const float* __restrict__ z, const float* __restrict__ cb,
             float* __restrict__ out_zq, float* __restrict__ out_idx,
             float* __restrict__ out) {
    extern __shared__ float smem[];
    float* z_s   = smem;
    float* e_s   = smem + ZS_F;
    float* esq_s = smem + ZS_F + ES_F;
    float* zsq_s = smem + ZS_F + ES_F + 1024;
    int*   s_idx = (int*)(smem + ZS_F + ES_F + 1024 + 64);
    float* swsum = smem + ZS_F + ES_F + 1024 + 128;

    const int t  = threadIdx.x;
    const int tx = t & 31;        // code lane (32 codes x 4 groups)
    const int ty = t >> 5;        // warp id == pixel group (8 px each)
    const int tile = blockIdx.x;            // 0..1023
    const int b    = tile >> 6;             // batch index (64 tiles per batch)
    const int hw0  = (tile & 63) << 6;      // hw offset (contiguous 64 pixels)

    // ---- CTA 0 pre-phase: compute all esq[k] (bit-exact sequential chain,
    //      software-pipelined loads), publish via flag. ~2us; never exposed
    //      because consumers only need esq after chunk-0 compute (~17us). ----
    if (tile == 0) {
        #pragma unroll 1
        for (int r = 0; r < 4; r++) {
            int k = r * 256 + t;
            const float4* row = (const float4*)(cb + (size_t)k * DDIM);
            float4 cur[8], nxt[8];
            #pragma unroll
            for (int i = 0; i < 8; i++) cur[i] = row[i];
            float s = 0.0f;
            #pragma unroll
            for (int bt = 0; bt < 8; bt++) {
                if (bt < 7) {
                    #pragma unroll
                    for (int i = 0; i < 8; i++) nxt[i] = row[(bt + 1) * 8 + i];
                }
                #pragma unroll
                for (int i = 0; i < 8; i++) {              // exact chain order
                    s = __fadd_rn(s, __fmul_rn(cur[i].x, cur[i].x));
                    s = __fadd_rn(s, __fmul_rn(cur[i].y, cur[i].y));
                    s = __fadd_rn(s, __fmul_rn(cur[i].z, cur[i].z));
                    s = __fadd_rn(s, __fmul_rn(cur[i].w, cur[i].w));
                }
                if (bt < 7) {
                    #pragma unroll
                    for (int i = 0; i < 8; i++) cur[i] = nxt[i];
                }
            }
            g_esq[k] = s;
        }
        __threadfence();
        __syncthreads();
        if (t == 0) atomicExch(&g_esq_flag, 1u);
    }

    const float* zb = z + (size_t)b * (DDIM * HW) + hw0;

    // Load z tile [256 c][64 px] into smem (coalesced: hw is fast axis)
    #pragma unroll
    for (int r = 0; r < 16; r++) {
        int e  = r * 256 + t;     // float4 task id, 4096 total
        int c  = e >> 4;
        int f4 = e & 15;
        float4 v = ((const float4*)(zb + (size_t)c * HW))[f4];
        *((float4*)&z_s[c * TILE_PX + f4 * 4]) = v;
    }
    __syncthreads();

    // Per-pixel zsq: sequential fp32 sum of z_c^2 (mul then add, exact chain)
    if (t < TILE_PX) {
        float s = 0.0f;
        for (int c = 0; c < DDIM; c++) {
            float v = z_s[c * TILE_PX + t];
            s = __fadd_rn(s, __fmul_rn(v, v));
        }
        zsq_s[t] = s;
    }
    __syncthreads();

    float zsqr[8];
    #pragma unroll
    for (int i = 0; i < 8; i++) zsqr[i] = zsq_s[ty * 8 + i];

    float bestd[8];
    int   bestk[8];
    #pragma unroll
    for (int i = 0; i < 8; i++) { bestd[i] = 3.4e38f; bestk[i] = 0; }

    for (int kt = 0; kt < NKT; kt++) {
        if (kt) __syncthreads();
        // Load codebook tile [128 k][256 c] -> e_s[k*257 + c]
        const float* cbt = cb + (size_t)kt * TILE_K * DDIM;
        #pragma unroll
        for (int i = 0; i < 32; i++) {
            int e  = i * 256 + t;     // 8192 float4 tasks
            int k  = e >> 6;
            int c4 = e & 63;
            float4 v = ((const float4*)(cbt + k * DDIM))[c4];
            float* dst = &e_s[k * 257 + c4 * 4];
            dst[0] = v.x; dst[1] = v.y; dst[2] = v.z; dst[3] = v.w;
        }
        __syncthreads();

        float acc[8][4];
        #pragma unroll
        for (int i = 0; i < 8; i++)
            #pragma unroll
            for (int j = 0; j < 4; j++) acc[i][j] = 0.0f;

        // dot products: 8 px x 4 codes per thread.
        // Single accumulator per element, ascending c, fused FMA chain
        // (bit-identical to the proven round-2/8/10 ordering).
        #pragma unroll 8
        for (int c = 0; c < DDIM; c++) {
            float4 za  = *((const float4*)&z_s[c * TILE_PX + ty * 8]);      // broadcast
            float4 zb4 = *((const float4*)&z_s[c * TILE_PX + ty * 8 + 4]);  // broadcast
            float rz0 = za.x, rz1 = za.y, rz2 = za.z, rz3 = za.w;
            float rz4 = zb4.x, rz5 = zb4.y, rz6 = zb4.z, rz7 = zb4.w;
            float re[4];
            #pragma unroll
            for (int j = 0; j < 4; j++)
                re[j] = e_s[(tx + 32 * j) * 257 + c];   // conflict-free: bank = tx+c
            #pragma unroll
            for (int j = 0; j < 4; j++) {
                acc[0][j] = fmaf(rz0, re[j], acc[0][j]);
                acc[1][j] = fmaf(rz1, re[j], acc[1][j]);
                acc[2][j] = fmaf(rz2, re[j], acc[2][j]);
                acc[3][j] = fmaf(rz3, re[j], acc[3][j]);
                acc[4][j] = fmaf(rz4, re[j], acc[4][j]);
                acc[5][j] = fmaf(rz5, re[j], acc[5][j]);
                acc[6][j] = fmaf(rz6, re[j], acc[6][j]);
                acc[7][j] = fmaf(rz7, re[j], acc[7][j]);
            }
        }

        // Before the FIRST distance step: ensure esq is published, then stage
        // it to smem. The spin is never exposed (chunk-0 compute >> pre-phase).
        if (kt == 0) {
            if (t == 0) {
                while (atomicAdd(&g_esq_flag, 0u) == 0u) { }
            }
            __syncthreads();
            ((float4*)esq_s)[t] = ((const float4*)g_esq)[t];   // 1024 floats
            __syncthreads();
        }

        // d = fl( fl(zsq + esq_k) - fl(2*dot) )   -- exact reference rounding.
        // k visited ascending per thread -> strict < keeps first-min.
        #pragma unroll
        for (int j = 0; j < 4; j++) {
            int kg = kt * TILE_K + tx + 32 * j;
            float eq = esq_s[kg];
            #pragma unroll
            for (int i = 0; i < 8; i++) {
                float t1 = __fadd_rn(zsqr[i], eq);
                float d  = __fsub_rn(t1, __fmul_rn(2.0f, acc[i][j]));
                if (d < bestd[i]) { bestd[i] = d; bestk[i] = kg; }
            }
        }
    }

    // Full-warp butterfly min-reduce with lowest-index tie-break
    #pragma unroll
    for (int i = 0; i < 8; i++) {
        float d = bestd[i];
        int   k = bestk[i];
        #pragma unroll
        for (int off = 16; off >= 1; off >>= 1) {
            float od = __shfl_xor_sync(0xFFFFFFFFu, d, off);
            int   ok = __shfl_xor_sync(0xFFFFFFFFu, k, off);
            if (od < d || (od == d && ok < k)) { d = od; k = ok; }
        }
        if (tx == 0) s_idx[ty * 8 + i] = k;
    }
    __syncthreads();

    // Epilogue: straight-through z_q write (coalesced), loss partial, idx write
    float lsum = 0.0f;
    float* out_base = out_zq + (size_t)b * (DDIM * HW) + hw0;
    #pragma unroll 4
    for (int r = 0; r < 64; r++) {
        int e  = r * 256 + t;       // 16384 elements
        int c  = e >> 6;
        int px = e & 63;
        int kk = s_idx[px];
        float q  = __ldg(&cb[(size_t)kk * DDIM + c]);
        float zv = z_s[c * TILE_PX + px];
        float dd = __fsub_rn(q, zv);                 // z_q - z
        lsum = fmaf(dd, dd, lsum);                   // loss partial
        out_base[(size_t)c * HW + px] = __fadd_rn(zv, dd);  // z + (z_q - z)
    }
    if (t < TILE_PX) out_idx[(size_t)tile * TILE_PX + t] = (float)s_idx[t];

    // block loss reduce + last-block finalize + cross-replay state reset
    #pragma unroll
    for (int off = 16; off >= 1; off >>= 1)
        lsum += __shfl_xor_sync(0xFFFFFFFFu, lsum, off);
    if ((t & 31) == 0) swsum[t >> 5] = lsum;
    __syncthreads();
    if (t == 0) {
        float bs = 0.0f;
        #pragma unroll
        for (int w = 0; w < 8; w++) bs += swsum[w];
        atomicAdd(&g_loss_acc, bs);
        __threadfence();
        unsigned n = atomicAdd(&g_done, 1u);
        if (n == NTILES - 1) {
            float m = __fmul_rn(g_loss_acc, 1.0f / (float)ZQ_ELEMS);  // /2^24 exact
            out[ZQ_ELEMS + NPX] = __fmul_rn(1.25f, m);
            // reset device state so the next graph replay is identical
            g_loss_acc = 0.0f;
            atomicExch(&g_esq_flag, 0u);
            __threadfence();
            atomicExch(&g_done, 0u);
        }
    }
}

extern "C" void kernel_launch(void* const* d_in, const int* in_sizes, int n_in,
                              void* d_out, int out_size) {
    const float* z  = (const float*)d_in[0];
    const float* cb = (const float*)d_in[1];
    float* out = (float*)d_out;

    // out layout: [z_q: 16777216][idx: 65536][loss: 1]
    float* out_zq  = out;
    float* out_idx = out + ZQ_ELEMS;

    size_t smem_bytes = SMEM_FLOATS * sizeof(float);
    cudaFuncSetAttribute(vq_main, cudaFuncAttributeMaxDynamicSharedMemorySize,
                         (int)smem_bytes);
    vq_main<<<NTILES, 256, smem_bytes>>>(z, cb, out_zq, out_idx, out);
}